// round 1
// baseline (speedup 1.0000x reference)
#include <cuda_runtime.h>

#define BSZ   2
#define SLEN_ 2048
#define DIM_  2048
#define NH_   16
#define DH_   128
#define MROWS (BSZ*SLEN_)   // 4096

// Scratch (device globals: allocation-free per harness rules)
__device__ float g_q[MROWS*DIM_];
__device__ float g_k[MROWS*DIM_];
__device__ float g_v[MROWS*DIM_];
__device__ float g_ctx[MROWS*DIM_];

// ---------------------------------------------------------------------------
// C[M,N] = A[M,K] @ W[N,K]^T + bias[N]   (torch Linear semantics, NT GEMM)
// 128x128 block tile, BK=16, 256 threads, 8x8 per thread, fp32.
// ---------------------------------------------------------------------------
__global__ __launch_bounds__(256, 2)
void gemm_nt_bias(const float* __restrict__ A, const float* __restrict__ W,
                  const float* __restrict__ bias, float* __restrict__ C,
                  int M, int N, int K)
{
    const int BK = 16;
    __shared__ float As[16][132];   // [k][m], padded
    __shared__ float Ws[16][132];   // [k][n], padded
    int tid = threadIdx.x;
    int tx = tid & 15, ty = tid >> 4;
    int bm = blockIdx.y * 128, bn = blockIdx.x * 128;

    float acc[8][8];
#pragma unroll
    for (int i = 0; i < 8; i++)
#pragma unroll
        for (int j = 0; j < 8; j++) acc[i][j] = 0.f;

    const float* Ap = A + (size_t)bm * K;
    const float* Wp = W + (size_t)bn * K;

    for (int k0 = 0; k0 < K; k0 += BK) {
#pragma unroll
        for (int i = 0; i < 2; i++) {
            int f = tid + i * 256;
            int row = f >> 2;
            int kq = (f & 3) << 2;
            float4 a = *(const float4*)(Ap + (size_t)row * K + k0 + kq);
            As[kq+0][row] = a.x; As[kq+1][row] = a.y;
            As[kq+2][row] = a.z; As[kq+3][row] = a.w;
            float4 w = *(const float4*)(Wp + (size_t)row * K + k0 + kq);
            Ws[kq+0][row] = w.x; Ws[kq+1][row] = w.y;
            Ws[kq+2][row] = w.z; Ws[kq+3][row] = w.w;
        }
        __syncthreads();
#pragma unroll
        for (int kk = 0; kk < BK; kk++) {
            float a[8], b[8];
            *(float4*)&a[0] = *(const float4*)&As[kk][ty*8];
            *(float4*)&a[4] = *(const float4*)&As[kk][ty*8+4];
            *(float4*)&b[0] = *(const float4*)&Ws[kk][tx*8];
            *(float4*)&b[4] = *(const float4*)&Ws[kk][tx*8+4];
#pragma unroll
            for (int i = 0; i < 8; i++)
#pragma unroll
                for (int j = 0; j < 8; j++)
                    acc[i][j] += a[i]*b[j];
        }
        __syncthreads();
    }

#pragma unroll
    for (int i = 0; i < 8; i++) {
        size_t row = (size_t)(bm + ty*8 + i);
#pragma unroll
        for (int j = 0; j < 8; j += 4) {
            int col = bn + tx*8 + j;
            float4 o;
            o.x = acc[i][j+0] + bias[col+0];
            o.y = acc[i][j+1] + bias[col+1];
            o.z = acc[i][j+2] + bias[col+2];
            o.w = acc[i][j+3] + bias[col+3];
            *(float4*)(C + row * N + col) = o;
        }
    }
}

// ---------------------------------------------------------------------------
// L2-normalize q and k over each 128-wide head-row; q also *= scale.
// One warp per head-row. First 65536 warps -> q, next 65536 -> k.
// ---------------------------------------------------------------------------
__global__ void norm_qk(float* __restrict__ q, float* __restrict__ k,
                        const float* __restrict__ scale_p)
{
    int gw = (int)((blockIdx.x * blockDim.x + threadIdx.x) >> 5);
    int lane = threadIdx.x & 31;
    const int NHR = MROWS * NH_;            // 65536 head-rows per tensor
    bool isq = gw < NHR;
    int r = isq ? gw : gw - NHR;
    float* base = (isq ? q : k) + (size_t)r * DH_;

    float4 v = ((const float4*)base)[lane];
    float ss = v.x*v.x + v.y*v.y + v.z*v.z + v.w*v.w;
#pragma unroll
    for (int d = 16; d > 0; d >>= 1) ss += __shfl_xor_sync(0xffffffffu, ss, d);
    float rinv = rsqrtf(ss);
    if (isq) rinv *= *scale_p;
    v.x *= rinv; v.y *= rinv; v.z *= rinv; v.w *= rinv;
    ((float4*)base)[lane] = v;
}

// ---------------------------------------------------------------------------
// Causal flash attention, fp32. One block per (b, h, 64-row q-tile).
// Online softmax; 256 threads; smem: sQ/sK [64][129], sV [64][128], sP [64][65]
// ---------------------------------------------------------------------------
__global__ __launch_bounds__(256, 1)
void flash_attn(const float* __restrict__ Q, const float* __restrict__ Kt,
                const float* __restrict__ V, float* __restrict__ O)
{
    extern __shared__ float sm[];
    float* sQ = sm;                  // [64][129]
    float* sK = sQ + 64*129;         // [64][129]
    float* sV = sK + 64*129;         // [64][128]
    float* sP = sV + 64*128;         // [64][65]

    int tid  = threadIdx.x;
    int lane = tid & 31;
    int warp = tid >> 5;
    int tx = tid & 15, ty = tid >> 4;
    int qt = blockIdx.x, h = blockIdx.y, b = blockIdx.z;
    int q0 = qt * 64;
    size_t base = (size_t)b * SLEN_ * DIM_ + (size_t)h * DH_;

    // load Q tile (rows q0..q0+63, 128 cols of this head)
#pragma unroll
    for (int rr = 0; rr < 8; rr++) {
        int r = warp*8 + rr;
        const float* src = Q + base + (size_t)(q0 + r) * DIM_;
#pragma unroll
        for (int i = 0; i < 4; i++)
            sQ[r*129 + i*32 + lane] = src[i*32 + lane];
    }

    float m_i[4], l_i[4], o[4][8];
#pragma unroll
    for (int i = 0; i < 4; i++) {
        m_i[i] = -1e30f; l_i[i] = 0.f;
#pragma unroll
        for (int j = 0; j < 8; j++) o[i][j] = 0.f;
    }

    for (int kt = 0; kt <= qt; kt++) {
        int k0 = kt * 64;
        __syncthreads();   // protect previous iter's sK/sV/sP consumers
#pragma unroll
        for (int rr = 0; rr < 8; rr++) {
            int r = warp*8 + rr;
            const float* ks = Kt + base + (size_t)(k0 + r) * DIM_;
            const float* vs = V  + base + (size_t)(k0 + r) * DIM_;
#pragma unroll
            for (int i = 0; i < 4; i++) {
                sK[r*129 + i*32 + lane] = ks[i*32 + lane];
                sV[r*128 + i*32 + lane] = vs[i*32 + lane];
            }
        }
        __syncthreads();

        // S = Q K^T  (64x64), thread computes 4x4 at rows ty*4+i, cols tx*4+j
        float s[4][4];
#pragma unroll
        for (int i = 0; i < 4; i++)
#pragma unroll
            for (int j = 0; j < 4; j++) s[i][j] = 0.f;

#pragma unroll 8
        for (int kk = 0; kk < 128; kk++) {
            float a[4], bb[4];
#pragma unroll
            for (int i = 0; i < 4; i++) a[i]  = sQ[(ty*4+i)*129 + kk];
#pragma unroll
            for (int j = 0; j < 4; j++) bb[j] = sK[(tx*4+j)*129 + kk];
#pragma unroll
            for (int i = 0; i < 4; i++)
#pragma unroll
                for (int j = 0; j < 4; j++)
                    s[i][j] += a[i]*bb[j];
        }

        if (kt == qt) {
#pragma unroll
            for (int i = 0; i < 4; i++)
#pragma unroll
                for (int j = 0; j < 4; j++)
                    if (tx*4+j > ty*4+i) s[i][j] = -1e30f;
        }

        // online softmax per q-row; row is owned by 16 threads (same ty)
#pragma unroll
        for (int i = 0; i < 4; i++) {
            float mx = fmaxf(fmaxf(s[i][0], s[i][1]), fmaxf(s[i][2], s[i][3]));
#pragma unroll
            for (int d = 1; d < 16; d <<= 1)
                mx = fmaxf(mx, __shfl_xor_sync(0xffffffffu, mx, d));
            float mnew  = fmaxf(m_i[i], mx);
            float alpha = __expf(m_i[i] - mnew);
            float rs = 0.f;
#pragma unroll
            for (int j = 0; j < 4; j++) {
                s[i][j] = __expf(s[i][j] - mnew);
                rs += s[i][j];
            }
#pragma unroll
            for (int d = 1; d < 16; d <<= 1)
                rs += __shfl_xor_sync(0xffffffffu, rs, d);
            l_i[i] = l_i[i]*alpha + rs;
            m_i[i] = mnew;
#pragma unroll
            for (int j = 0; j < 8; j++) o[i][j] *= alpha;
#pragma unroll
            for (int j = 0; j < 4; j++) sP[(ty*4+i)*65 + tx*4+j] = s[i][j];
        }
        __syncthreads();

        // O += P V  (64x128), thread owns rows ty*4+i, cols tx + 16*j
#pragma unroll 4
        for (int kk = 0; kk < 64; kk++) {
            float pi[4], vv[8];
#pragma unroll
            for (int i = 0; i < 4; i++) pi[i] = sP[(ty*4+i)*65 + kk];
#pragma unroll
            for (int j = 0; j < 8; j++) vv[j] = sV[kk*128 + tx + 16*j];
#pragma unroll
            for (int i = 0; i < 4; i++)
#pragma unroll
                for (int j = 0; j < 8; j++)
                    o[i][j] += pi[i]*vv[j];
        }
    }

#pragma unroll
    for (int i = 0; i < 4; i++) {
        float inv = 1.f / l_i[i];
        float* dst = O + base + (size_t)(q0 + ty*4 + i) * DIM_;
#pragma unroll
        for (int j = 0; j < 8; j++) dst[tx + 16*j] = o[i][j] * inv;
    }
}

// ---------------------------------------------------------------------------
// inputs (metadata order): x, mask, Wq, bq, Wk, bk, Wv, bv, Wo, bo, scale
// mask is analytically causal (tril) -> ignored.
// ---------------------------------------------------------------------------
extern "C" void kernel_launch(void* const* d_in, const int* in_sizes, int n_in,
                              void* d_out, int out_size)
{
    (void)in_sizes; (void)n_in; (void)out_size;
    const float* x     = (const float*)d_in[0];
    const float* Wq    = (const float*)d_in[2];
    const float* bq    = (const float*)d_in[3];
    const float* Wk    = (const float*)d_in[4];
    const float* bk    = (const float*)d_in[5];
    const float* Wv    = (const float*)d_in[6];
    const float* bv    = (const float*)d_in[7];
    const float* Wo    = (const float*)d_in[8];
    const float* bo    = (const float*)d_in[9];
    const float* scale = (const float*)d_in[10];
    float* out = (float*)d_out;

    float *q, *k, *v, *ctx;
    cudaGetSymbolAddress((void**)&q,   g_q);
    cudaGetSymbolAddress((void**)&k,   g_k);
    cudaGetSymbolAddress((void**)&v,   g_v);
    cudaGetSymbolAddress((void**)&ctx, g_ctx);

    dim3 gg(DIM_/128, MROWS/128);   // (16, 32)
    gemm_nt_bias<<<gg, 256>>>(x, Wq, bq, q, MROWS, DIM_, DIM_);
    gemm_nt_bias<<<gg, 256>>>(x, Wk, bk, k, MROWS, DIM_, DIM_);
    gemm_nt_bias<<<gg, 256>>>(x, Wv, bv, v, MROWS, DIM_, DIM_);

    norm_qk<<<16384, 256>>>(q, k, scale);

    const int FLASH_SMEM = (64*129*2 + 64*128 + 64*65) * 4;  // 115456 B
    cudaFuncSetAttribute((const void*)flash_attn,
                         cudaFuncAttributeMaxDynamicSharedMemorySize, FLASH_SMEM);
    flash_attn<<<dim3(SLEN_/64, NH_, BSZ), 256, FLASH_SMEM>>>(q, k, v, ctx);

    gemm_nt_bias<<<gg, 256>>>(ctx, Wo, bo, out, MROWS, DIM_, DIM_);
}

// round 2
// speedup vs baseline: 1.9491x; 1.9491x over previous
#include <cuda_runtime.h>

#define BSZ   2
#define SLEN_ 2048
#define DIM_  2048
#define NH_   16
#define DH_   128
#define MROWS (BSZ*SLEN_)   // 4096

// Scratch (device globals: allocation-free per harness rules)
__device__ float g_q[MROWS*DIM_];
__device__ float g_k[MROWS*DIM_];
__device__ float g_v[MROWS*DIM_];
__device__ float g_ctx[MROWS*DIM_];

__device__ __forceinline__ unsigned f2tf(float x) {
    unsigned r; asm("cvt.rna.tf32.f32 %0, %1;" : "=r"(r) : "f"(x)); return r;
}
__device__ __forceinline__ unsigned sptr(const void* p) {
    return (unsigned)__cvta_generic_to_shared(p);
}

// ---------------------------------------------------------------------------
// C[M,N] = A[M,K] @ W[N,K]^T + bias[N], tf32 tensor cores.
// 128x128x32 block tile, 256 thr = 8 warps (2x4), warp tile 64x32,
// m16n8k8 mma, cp.async double buffer. Dyn smem 73728 B.
// ---------------------------------------------------------------------------
#define BM 128
#define BN 128
#define BK 32
#define KS 36   // BK + 4 pad: fragment gathers conflict-free

__global__ __launch_bounds__(256, 2)
void gemm_tf32_nt(const float* __restrict__ A, const float* __restrict__ W,
                  const float* __restrict__ bias, float* __restrict__ C,
                  int M, int N, int K)
{
    extern __shared__ float smbuf[];
    float* As = smbuf;               // [2][BM*KS]
    float* Ws = smbuf + 2 * BM * KS; // [2][BN*KS]

    int tid = threadIdx.x, lane = tid & 31, w = tid >> 5;
    int wm = (w >> 2) * 64, wn = (w & 3) * 32;
    int bm = blockIdx.y * BM, bn = blockIdx.x * BN;
    const float* Ap = A + (size_t)bm * K;
    const float* Wp = W + (size_t)bn * K;

    float acc[4][4][4];
#pragma unroll
    for (int mt = 0; mt < 4; mt++)
#pragma unroll
        for (int nt = 0; nt < 4; nt++)
#pragma unroll
            for (int r = 0; r < 4; r++) acc[mt][nt][r] = 0.f;

    auto stage = [&](int buf, int k0) {
        float* ad = As + buf * BM * KS;
        float* wd = Ws + buf * BN * KS;
#pragma unroll
        for (int i = 0; i < 4; i++) {
            int c = tid + i * 256;
            int row = c >> 3, kc = (c & 7) << 2;
            asm volatile("cp.async.cg.shared.global [%0], [%1], 16;"
                :: "r"(sptr(ad + row * KS + kc)),
                   "l"(Ap + (size_t)row * K + k0 + kc));
            asm volatile("cp.async.cg.shared.global [%0], [%1], 16;"
                :: "r"(sptr(wd + row * KS + kc)),
                   "l"(Wp + (size_t)row * K + k0 + kc));
        }
    };

    stage(0, 0);
    asm volatile("cp.async.commit_group;");
    asm volatile("cp.async.wait_group 0;");
    __syncthreads();

    int NT = K / BK;
    for (int kt = 0; kt < NT; kt++) {
        int buf = kt & 1;
        if (kt + 1 < NT) {
            stage(buf ^ 1, (kt + 1) * BK);
            asm volatile("cp.async.commit_group;");
        }
        const float* a0 = As + buf * BM * KS;
        const float* w0 = Ws + buf * BN * KS;
#pragma unroll
        for (int k8 = 0; k8 < BK; k8 += 8) {
            unsigned af[4][4], bf[4][2];
#pragma unroll
            for (int mt = 0; mt < 4; mt++) {
                const float* p = a0 + (wm + mt*16 + (lane >> 2)) * KS + k8 + (lane & 3);
                af[mt][0] = f2tf(p[0]);
                af[mt][1] = f2tf(p[8*KS]);
                af[mt][2] = f2tf(p[4]);
                af[mt][3] = f2tf(p[8*KS + 4]);
            }
#pragma unroll
            for (int nt = 0; nt < 4; nt++) {
                const float* p = w0 + (wn + nt*8 + (lane >> 2)) * KS + k8 + (lane & 3);
                bf[nt][0] = f2tf(p[0]);
                bf[nt][1] = f2tf(p[4]);
            }
#pragma unroll
            for (int mt = 0; mt < 4; mt++)
#pragma unroll
                for (int nt = 0; nt < 4; nt++)
                    asm volatile(
                        "mma.sync.aligned.m16n8k8.row.col.f32.tf32.tf32.f32 "
                        "{%0,%1,%2,%3}, {%4,%5,%6,%7}, {%8,%9}, {%0,%1,%2,%3};"
                        : "+f"(acc[mt][nt][0]), "+f"(acc[mt][nt][1]),
                          "+f"(acc[mt][nt][2]), "+f"(acc[mt][nt][3])
                        : "r"(af[mt][0]), "r"(af[mt][1]), "r"(af[mt][2]), "r"(af[mt][3]),
                          "r"(bf[nt][0]), "r"(bf[nt][1]));
        }
        if (kt + 1 < NT) asm volatile("cp.async.wait_group 0;");
        __syncthreads();
    }

    // epilogue: c0/c1 at (row, col..col+1), c2/c3 at (row+8, ...)
#pragma unroll
    for (int nt = 0; nt < 4; nt++) {
        int col = bn + wn + nt * 8 + (lane & 3) * 2;
        float2 bv = *(const float2*)(bias + col);
#pragma unroll
        for (int mt = 0; mt < 4; mt++) {
            int r0 = bm + wm + mt * 16 + (lane >> 2);
            float2 o0 = { acc[mt][nt][0] + bv.x, acc[mt][nt][1] + bv.y };
            float2 o1 = { acc[mt][nt][2] + bv.x, acc[mt][nt][3] + bv.y };
            *(float2*)(C + (size_t)r0 * N + col) = o0;
            *(float2*)(C + (size_t)(r0 + 8) * N + col) = o1;
        }
    }
}

// ---------------------------------------------------------------------------
// L2-normalize q and k over each 128-wide head-row; q also *= scale.
// ---------------------------------------------------------------------------
__global__ void norm_qk(float* __restrict__ q, float* __restrict__ k,
                        const float* __restrict__ scale_p)
{
    int gw = (int)((blockIdx.x * blockDim.x + threadIdx.x) >> 5);
    int lane = threadIdx.x & 31;
    const int NHR = MROWS * NH_;
    bool isq = gw < NHR;
    int r = isq ? gw : gw - NHR;
    float* base = (isq ? q : k) + (size_t)r * DH_;

    float4 v = ((const float4*)base)[lane];
    float ss = v.x*v.x + v.y*v.y + v.z*v.z + v.w*v.w;
#pragma unroll
    for (int d = 16; d > 0; d >>= 1) ss += __shfl_xor_sync(0xffffffffu, ss, d);
    float rinv = rsqrtf(ss);
    if (isq) rinv *= *scale_p;
    v.x *= rinv; v.y *= rinv; v.z *= rinv; v.w *= rinv;
    ((float4*)base)[lane] = v;
}

// ---------------------------------------------------------------------------
// Causal flash attention, fp32 SIMT (unchanged this round).
// ---------------------------------------------------------------------------
__global__ __launch_bounds__(256, 1)
void flash_attn(const float* __restrict__ Q, const float* __restrict__ Kt,
                const float* __restrict__ V, float* __restrict__ O)
{
    extern __shared__ float sm[];
    float* sQ = sm;                  // [64][129]
    float* sK = sQ + 64*129;         // [64][129]
    float* sV = sK + 64*129;         // [64][128]
    float* sP = sV + 64*128;         // [64][65]

    int tid  = threadIdx.x;
    int lane = tid & 31;
    int warp = tid >> 5;
    int tx = tid & 15, ty = tid >> 4;
    int qt = blockIdx.x, h = blockIdx.y, b = blockIdx.z;
    int q0 = qt * 64;
    size_t base = (size_t)b * SLEN_ * DIM_ + (size_t)h * DH_;

#pragma unroll
    for (int rr = 0; rr < 8; rr++) {
        int r = warp*8 + rr;
        const float* src = Q + base + (size_t)(q0 + r) * DIM_;
#pragma unroll
        for (int i = 0; i < 4; i++)
            sQ[r*129 + i*32 + lane] = src[i*32 + lane];
    }

    float m_i[4], l_i[4], o[4][8];
#pragma unroll
    for (int i = 0; i < 4; i++) {
        m_i[i] = -1e30f; l_i[i] = 0.f;
#pragma unroll
        for (int j = 0; j < 8; j++) o[i][j] = 0.f;
    }

    for (int kt = 0; kt <= qt; kt++) {
        int k0 = kt * 64;
        __syncthreads();
#pragma unroll
        for (int rr = 0; rr < 8; rr++) {
            int r = warp*8 + rr;
            const float* ks = Kt + base + (size_t)(k0 + r) * DIM_;
            const float* vs = V  + base + (size_t)(k0 + r) * DIM_;
#pragma unroll
            for (int i = 0; i < 4; i++) {
                sK[r*129 + i*32 + lane] = ks[i*32 + lane];
                sV[r*128 + i*32 + lane] = vs[i*32 + lane];
            }
        }
        __syncthreads();

        float s[4][4];
#pragma unroll
        for (int i = 0; i < 4; i++)
#pragma unroll
            for (int j = 0; j < 4; j++) s[i][j] = 0.f;

#pragma unroll 8
        for (int kk = 0; kk < 128; kk++) {
            float a[4], bb[4];
#pragma unroll
            for (int i = 0; i < 4; i++) a[i]  = sQ[(ty*4+i)*129 + kk];
#pragma unroll
            for (int j = 0; j < 4; j++) bb[j] = sK[(tx*4+j)*129 + kk];
#pragma unroll
            for (int i = 0; i < 4; i++)
#pragma unroll
                for (int j = 0; j < 4; j++)
                    s[i][j] += a[i]*bb[j];
        }

        if (kt == qt) {
#pragma unroll
            for (int i = 0; i < 4; i++)
#pragma unroll
                for (int j = 0; j < 4; j++)
                    if (tx*4+j > ty*4+i) s[i][j] = -1e30f;
        }

#pragma unroll
        for (int i = 0; i < 4; i++) {
            float mx = fmaxf(fmaxf(s[i][0], s[i][1]), fmaxf(s[i][2], s[i][3]));
#pragma unroll
            for (int d = 1; d < 16; d <<= 1)
                mx = fmaxf(mx, __shfl_xor_sync(0xffffffffu, mx, d));
            float mnew  = fmaxf(m_i[i], mx);
            float alpha = __expf(m_i[i] - mnew);
            float rs = 0.f;
#pragma unroll
            for (int j = 0; j < 4; j++) {
                s[i][j] = __expf(s[i][j] - mnew);
                rs += s[i][j];
            }
#pragma unroll
            for (int d = 1; d < 16; d <<= 1)
                rs += __shfl_xor_sync(0xffffffffu, rs, d);
            l_i[i] = l_i[i]*alpha + rs;
            m_i[i] = mnew;
#pragma unroll
            for (int j = 0; j < 8; j++) o[i][j] *= alpha;
#pragma unroll
            for (int j = 0; j < 4; j++) sP[(ty*4+i)*65 + tx*4+j] = s[i][j];
        }
        __syncthreads();

#pragma unroll 4
        for (int kk = 0; kk < 64; kk++) {
            float pi[4], vv[8];
#pragma unroll
            for (int i = 0; i < 4; i++) pi[i] = sP[(ty*4+i)*65 + kk];
#pragma unroll
            for (int j = 0; j < 8; j++) vv[j] = sV[kk*128 + tx + 16*j];
#pragma unroll
            for (int i = 0; i < 4; i++)
#pragma unroll
                for (int j = 0; j < 8; j++)
                    o[i][j] += pi[i]*vv[j];
        }
    }

#pragma unroll
    for (int i = 0; i < 4; i++) {
        float inv = 1.f / l_i[i];
        float* dst = O + base + (size_t)(q0 + ty*4 + i) * DIM_;
#pragma unroll
        for (int j = 0; j < 8; j++) dst[tx + 16*j] = o[i][j] * inv;
    }
}

// ---------------------------------------------------------------------------
// inputs: x, mask, Wq, bq, Wk, bk, Wv, bv, Wo, bo, scale (mask ignored: tril)
// ---------------------------------------------------------------------------
extern "C" void kernel_launch(void* const* d_in, const int* in_sizes, int n_in,
                              void* d_out, int out_size)
{
    (void)in_sizes; (void)n_in; (void)out_size;
    const float* x     = (const float*)d_in[0];
    const float* Wq    = (const float*)d_in[2];
    const float* bq    = (const float*)d_in[3];
    const float* Wk    = (const float*)d_in[4];
    const float* bk    = (const float*)d_in[5];
    const float* Wv    = (const float*)d_in[6];
    const float* bv    = (const float*)d_in[7];
    const float* Wo    = (const float*)d_in[8];
    const float* bo    = (const float*)d_in[9];
    const float* scale = (const float*)d_in[10];
    float* out = (float*)d_out;

    float *q, *k, *v, *ctx;
    cudaGetSymbolAddress((void**)&q,   g_q);
    cudaGetSymbolAddress((void**)&k,   g_k);
    cudaGetSymbolAddress((void**)&v,   g_v);
    cudaGetSymbolAddress((void**)&ctx, g_ctx);

    const int GEMM_SMEM = 2 * (BM * KS + BN * KS) * 4;  // 73728 B
    cudaFuncSetAttribute((const void*)gemm_tf32_nt,
                         cudaFuncAttributeMaxDynamicSharedMemorySize, GEMM_SMEM);

    dim3 gg(DIM_/BN, MROWS/BM);   // (16, 32)
    gemm_tf32_nt<<<gg, 256, GEMM_SMEM>>>(x, Wq, bq, q, MROWS, DIM_, DIM_);
    gemm_tf32_nt<<<gg, 256, GEMM_SMEM>>>(x, Wk, bk, k, MROWS, DIM_, DIM_);
    gemm_tf32_nt<<<gg, 256, GEMM_SMEM>>>(x, Wv, bv, v, MROWS, DIM_, DIM_);

    norm_qk<<<16384, 256>>>(q, k, scale);

    const int FLASH_SMEM = (64*129*2 + 64*128 + 64*65) * 4;  // 115456 B
    cudaFuncSetAttribute((const void*)flash_attn,
                         cudaFuncAttributeMaxDynamicSharedMemorySize, FLASH_SMEM);
    flash_attn<<<dim3(SLEN_/64, NH_, BSZ), 256, FLASH_SMEM>>>(q, k, v, ctx);

    gemm_tf32_nt<<<gg, 256, GEMM_SMEM>>>(ctx, Wo, bo, out, MROWS, DIM_, DIM_);
}